// round 7
// baseline (speedup 1.0000x reference)
#include <cuda_runtime.h>
#include <cuda_bf16.h>
#include <cstdint>

// MoE router: jitter -> GEMM (16384x4096 @ 4096x64) -> softmax -> biased top-8
// -> L2-norm weights -> bincount.  GEMM via legacy mma.sync.m16n8k16.bf16,
// 3xBF16 split.  512 threads/CTA (4 warps/SMSP) for latency hiding:
// 8 token-groups (m16 warp tiles) x 2 K-sets.  Near-tie tokens repaired in fp32.

#define N_TOK   16384
#define DIM     4096
#define NEXP    64
#define TOPK    8
#define NCAND   12
#define MT      128
#define KC      32              // K per chunk = 16 kp words = 2 k16-steps
#define NCHUNK  (DIM / KC)      // 128
#define THREADS 512
#define NBLK    (N_TOK / MT)    // 128
#define THRESH  2e-5f

#define OFF_LOGITS 0
#define OFF_SCORES (N_TOK * NEXP)
#define OFF_W      (2 * N_TOK * NEXP)
#define OFF_IDX    (2 * N_TOK * NEXP + N_TOK * TOPK)
#define OFF_CNT    (2 * N_TOK * NEXP + 2 * N_TOK * TOPK)

// dynamic smem, per buf 24576 B:
//   A_hi [16 kp][128 tok] u32 : 8192 B ; A_lo +8192 ; B_hi [16][64] : 4096 ; B_lo
#define AHIB(b) ((b) * 24576)
#define ALOB(b) ((b) * 24576 + 8192)
#define BHIB(b) ((b) * 24576 + 16384)
#define BLOB(b) ((b) * 24576 + 20480)
#define SMEM_BYTES 49152

typedef unsigned long long u64;

// XOR'ed word index within an A plane / B plane (bank-conflict-free both sides)
#define AW(kp, tok) ((kp) * 128 + ((tok) ^ (((kp) & 3) << 3)))
#define BW(kp, e)   ((kp) * 64  + ((e)   ^ (((kp) & 3) << 3)))

__device__ uint32_t g_Bh[NCHUNK * 16 * NEXP];   // [chunk][kp][e^xor] packed bf16x2
__device__ uint32_t g_Bl[NCHUNK * 16 * NEXP];
__device__ float g_WT[NEXP * DIM];              // [e][k] fp32 for repair
__device__ int g_nflag;
__device__ int g_list[N_TOK];
__device__ int g_cand[N_TOK * NCAND];

__device__ __forceinline__ uint32_t pack_bf16x2(float hi_elem, float lo_elem) {
    uint32_t d;
    asm("cvt.rn.bf16x2.f32 %0, %1, %2;" : "=r"(d) : "f"(hi_elem), "f"(lo_elem));
    return d;
}

__device__ __forceinline__ void mma_bf16(float* c,
                                         uint32_t a0, uint32_t a1, uint32_t a2, uint32_t a3,
                                         uint32_t b0, uint32_t b1) {
    asm volatile(
        "mma.sync.aligned.m16n8k16.row.col.f32.bf16.bf16.f32 "
        "{%0,%1,%2,%3}, {%4,%5,%6,%7}, {%8,%9}, {%0,%1,%2,%3};"
        : "+f"(c[0]), "+f"(c[1]), "+f"(c[2]), "+f"(c[3])
        : "r"(a0), "r"(a1), "r"(a2), "r"(a3), "r"(b0), "r"(b1));
}

__global__ void zero_cnt_kernel(float* g) {
    g[threadIdx.x] = 0.0f;
    if (threadIdx.x == 0) g_nflag = 0;
}

__global__ void prep_W_kernel(const float* __restrict__ W) {
    int p = blockIdx.x * 256 + threadIdx.x;       // 131072
    int e     = p & 63;
    int kp    = (p >> 6) & 15;
    int chunk = p >> 10;
    int k = chunk * KC + 2 * kp;
    float w0 = W[(size_t)k * NEXP + e];
    float w1 = W[(size_t)(k + 1) * NEXP + e];
    uint32_t h = pack_bf16x2(w1, w0);
    float r0 = w0 - __uint_as_float(h << 16);
    float r1 = w1 - __uint_as_float(h & 0xFFFF0000u);
    uint32_t l = pack_bf16x2(r1, r0);
    int idx = chunk * 1024 + BW(kp, e);
    g_Bh[idx] = h;
    g_Bl[idx] = l;
    g_WT[(size_t)e * DIM + k]     = w0;
    g_WT[(size_t)e * DIM + k + 1] = w1;
}

__global__ void __launch_bounds__(THREADS, 1)
router_kernel(const float* __restrict__ x, const float* __restrict__ sbias_g,
              const float* __restrict__ noise, float* __restrict__ out) {
    extern __shared__ char db[];
    __shared__ float s_bias[NEXP];

    const int tid  = threadIdx.x;
    const int wid  = tid >> 5;
    const int lane = tid & 31;
    const int g    = lane >> 2;
    const int tig  = lane & 3;
    const int set  = wid >> 3;                // K-set (k16 step within chunk)
    const int wTok = (wid & 7) * 16;          // warp token base (m16 tile)
    const int tok0 = blockIdx.x * MT;

    if (tid < NEXP) s_bias[tid] = sbias_g[tid];

    // staging: thread -> (token, k-quarter of 8 elems = 4 kp)
    const int t_tok = tid & 127;
    const int t_q   = tid >> 7;               // 0..3
    const float* xg = x     + (size_t)(tok0 + t_tok) * DIM + t_q * 8;
    const float* ng = noise + (size_t)(tok0 + t_tok) * DIM + t_q * 8;
    const uint2* pBh2 = (const uint2*)g_Bh;    // 512 uint2 per chunk
    const uint2* pBl2 = (const uint2*)g_Bl;

    float acc[8][4];
#pragma unroll
    for (int j = 0; j < 8; ++j)
#pragma unroll
        for (int q = 0; q < 4; ++q) acc[j][q] = 0.0f;

    float4 rx[2], rn[2];
    uint2  rbh, rbl;

#pragma unroll
    for (int j = 0; j < 2; ++j) {
        rx[j] = *(const float4*)(xg + 4 * j);
        rn[j] = *(const float4*)(ng + 4 * j);
    }
    rbh = pBh2[tid];
    rbl = pBl2[tid];

#define STORE_CHUNK(BUF) do {                                                   \
        uint32_t* Ah = (uint32_t*)(db + AHIB(BUF));                             \
        uint32_t* Al = (uint32_t*)(db + ALOB(BUF));                             \
        _Pragma("unroll")                                                       \
        for (int j = 0; j < 2; ++j) {                                           \
            float v0 = rx[j].x * (0.99f + rn[j].x * 0.02f);                     \
            float v1 = rx[j].y * (0.99f + rn[j].y * 0.02f);                     \
            float v2 = rx[j].z * (0.99f + rn[j].z * 0.02f);                     \
            float v3 = rx[j].w * (0.99f + rn[j].w * 0.02f);                     \
            uint32_t h0 = pack_bf16x2(v1, v0);                                  \
            uint32_t h1 = pack_bf16x2(v3, v2);                                  \
            float r0 = v0 - __uint_as_float(h0 << 16);                          \
            float r1 = v1 - __uint_as_float(h0 & 0xFFFF0000u);                  \
            float r2 = v2 - __uint_as_float(h1 << 16);                          \
            float r3 = v3 - __uint_as_float(h1 & 0xFFFF0000u);                  \
            uint32_t l0 = pack_bf16x2(r1, r0);                                  \
            uint32_t l1 = pack_bf16x2(r3, r2);                                  \
            int kp0 = t_q * 4 + 2 * j;                                          \
            Ah[AW(kp0, t_tok)]     = h0;                                        \
            Ah[AW(kp0 + 1, t_tok)] = h1;                                        \
            Al[AW(kp0, t_tok)]     = l0;                                        \
            Al[AW(kp0 + 1, t_tok)] = l1;                                        \
        }                                                                       \
        ((uint2*)(db + BHIB(BUF)))[tid] = rbh;                                  \
        ((uint2*)(db + BLOB(BUF)))[tid] = rbl;                                  \
    } while (0)

    STORE_CHUNK(0);
    __syncthreads();

#pragma unroll 1
    for (int c = 0; c < NCHUNK; ++c) {
        const int buf = c & 1;
        const bool more = (c + 1 < NCHUNK);

        if (more) {
            const int cb = (c + 1) * KC;
#pragma unroll
            for (int j = 0; j < 2; ++j) {
                rx[j] = *(const float4*)(xg + cb + 4 * j);
                rn[j] = *(const float4*)(ng + cb + 4 * j);
            }
            rbh = pBh2[(c + 1) * 512 + tid];
            rbl = pBl2[(c + 1) * 512 + tid];
        }

        // ---- my k16 step of this chunk: kp in [set*8, set*8+8) ----
        {
            const uint32_t* Ah = (const uint32_t*)(db + AHIB(buf));
            const uint32_t* Al = (const uint32_t*)(db + ALOB(buf));
            const uint32_t* Bh = (const uint32_t*)(db + BHIB(buf));
            const uint32_t* Bl = (const uint32_t*)(db + BLOB(buf));
            const int kb = set * 8;
            const int tr = wTok + g;

            uint32_t ah[4], al[4], b[8][2];
            ah[0] = Ah[AW(kb + tig, tr)];
            ah[1] = Ah[AW(kb + tig, tr + 8)];
            ah[2] = Ah[AW(kb + tig + 4, tr)];
            ah[3] = Ah[AW(kb + tig + 4, tr + 8)];
#pragma unroll
            for (int j = 0; j < 8; ++j) {
                b[j][0] = Bh[BW(kb + tig, j * 8 + g)];
                b[j][1] = Bh[BW(kb + tig + 4, j * 8 + g)];
            }
            // T1: a_hi * b_hi
#pragma unroll
            for (int j = 0; j < 8; ++j)
                mma_bf16(acc[j], ah[0], ah[1], ah[2], ah[3], b[j][0], b[j][1]);
            // T3: a_lo * b_hi  (b regs still hold Bh)
            al[0] = Al[AW(kb + tig, tr)];
            al[1] = Al[AW(kb + tig, tr + 8)];
            al[2] = Al[AW(kb + tig + 4, tr)];
            al[3] = Al[AW(kb + tig + 4, tr + 8)];
#pragma unroll
            for (int j = 0; j < 8; ++j)
                mma_bf16(acc[j], al[0], al[1], al[2], al[3], b[j][0], b[j][1]);
            // T2: a_hi * b_lo  (reuse b regs)
#pragma unroll
            for (int j = 0; j < 8; ++j) {
                b[j][0] = Bl[BW(kb + tig, j * 8 + g)];
                b[j][1] = Bl[BW(kb + tig + 4, j * 8 + g)];
            }
#pragma unroll
            for (int j = 0; j < 8; ++j)
                mma_bf16(acc[j], ah[0], ah[1], ah[2], ah[3], b[j][0], b[j][1]);
        }

        if (more) STORE_CHUNK(buf ^ 1);
        __syncthreads();
    }

    // ---- epilogue: K-set reduction into L[128][65] ----
    float* L = (float*)db;
    if (set == 0) {
#pragma unroll
        for (int j = 0; j < 8; ++j) {
            int r = wTok + g, cb = j * 8 + tig * 2;
            L[r * 65 + cb]           = acc[j][0];
            L[r * 65 + cb + 1]       = acc[j][1];
            L[(r + 8) * 65 + cb]     = acc[j][2];
            L[(r + 8) * 65 + cb + 1] = acc[j][3];
        }
    }
    __syncthreads();
    if (set == 1) {
#pragma unroll
        for (int j = 0; j < 8; ++j) {
            int r = wTok + g, cb = j * 8 + tig * 2;
            L[r * 65 + cb]           += acc[j][0];
            L[r * 65 + cb + 1]       += acc[j][1];
            L[(r + 8) * 65 + cb]     += acc[j][2];
            L[(r + 8) * 65 + cb + 1] += acc[j][3];
        }
    }
    __syncthreads();

    float* gL = out + OFF_LOGITS + (size_t)tok0 * NEXP;
    for (int idx = tid; idx < MT * NEXP; idx += THREADS)
        gL[idx] = L[(idx >> 6) * 65 + (idx & 63)];
    __syncthreads();

    if (tid < MT) {
        float* row = L + tid * 65;
        float mx = row[0];
#pragma unroll 8
        for (int e = 1; e < NEXP; ++e) mx = fmaxf(mx, row[e]);
        float s = 0.0f;
#pragma unroll 8
        for (int e = 0; e < NEXP; ++e) s += expf(row[e] - mx);
        float inv = 1.0f / s;
#pragma unroll 8
        for (int e = 0; e < NEXP; ++e) row[e] = expf(row[e] - mx) * inv;
    }
    __syncthreads();

    float* gS = out + OFF_SCORES + (size_t)tok0 * NEXP;
    for (int idx = tid; idx < MT * NEXP; idx += THREADS)
        gS[idx] = L[(idx >> 6) * 65 + (idx & 63)];

    // top-12 biased ranking; write top-8; flag near-ties for exact-fp32 repair
    if (tid < MT) {
        const float* rp = L + tid * 65;
        float bv[NCAND];
        int   bix[NCAND];
        u64 mask = 0ull;
#pragma unroll
        for (int k = 0; k < NCAND; ++k) {
            float best = -1e30f;
            int bi = 0;
            for (int e = 0; e < NEXP; ++e) {
                if (!((mask >> e) & 1ull)) {
                    float v = rp[e] + s_bias[e];
                    if (v > best) { best = v; bi = e; }
                }
            }
            mask |= 1ull << bi;
            bv[k] = best;
            bix[k] = bi;
        }
        float w[TOPK], ss = 0.0f;
#pragma unroll
        for (int k = 0; k < TOPK; ++k) { w[k] = rp[bix[k]]; ss += w[k] * w[k]; }
        float winv = 1.0f / sqrtf(ss);

        const int tok = tok0 + tid;
        float* gW = out + OFF_W   + (size_t)tok * TOPK;
        float* gI = out + OFF_IDX + (size_t)tok * TOPK;
#pragma unroll
        for (int k = 0; k < TOPK; ++k) {
            gW[k] = w[k] * winv;
            gI[k] = (float)bix[k];
        }

        float ming = bv[0] - bv[1];
#pragma unroll
        for (int j = 1; j < 8; ++j) ming = fminf(ming, bv[j] - bv[j + 1]);
        if (ming < THRESH) {
            int pos = atomicAdd(&g_nflag, 1);
            g_list[pos] = tok;
#pragma unroll
            for (int j = 0; j < NCAND; ++j) g_cand[tok * NCAND + j] = bix[j];
        }
    }
}

// Repair: recompute 12 candidate logits in exact fp32 for flagged tokens,
// re-rank, rewrite indices + weights (weights gathered from MMA scores row).
__global__ void __launch_bounds__(384, 2)
repair_kernel(const float* __restrict__ x, const float* __restrict__ sbias_g,
              const float* __restrict__ noise, float* __restrict__ out) {
    __shared__ float sxj[DIM];
    __shared__ float sl[NCAND];
    __shared__ int   se[NCAND];

    const int tid  = threadIdx.x;
    const int wid  = tid >> 5;
    const int lane = tid & 31;
    const int n    = g_nflag;

    for (int i = blockIdx.x; i < n; i += gridDim.x) {
        const int tok = g_list[i];
        __syncthreads();

        const float* xr = x     + (size_t)tok * DIM;
        const float* nr = noise + (size_t)tok * DIM;
        for (int idx = tid; idx < DIM; idx += 384)
            sxj[idx] = xr[idx] * (0.99f + nr[idx] * 0.02f);
        __syncthreads();

        if (wid < NCAND) {
            const int e = g_cand[tok * NCAND + wid];
            const float* wt = g_WT + (size_t)e * DIM;
            float a = 0.0f;
            for (int k = lane; k < DIM; k += 32 * 4) {
                a += sxj[k]       * wt[k];
                a += sxj[k + 32]  * wt[k + 32];
                a += sxj[k + 64]  * wt[k + 64];
                a += sxj[k + 96]  * wt[k + 96];
            }
#pragma unroll
            for (int o = 16; o; o >>= 1) a += __shfl_xor_sync(0xFFFFFFFFu, a, o);
            if (lane == 0) { sl[wid] = a; se[wid] = e; }
        }
        __syncthreads();

        if (tid == 0) {
            float mxl = sl[0];
#pragma unroll
            for (int j = 1; j < NCAND; ++j) mxl = fmaxf(mxl, sl[j]);
            float s0 = out[OFF_SCORES + (size_t)tok * NEXP + se[0]];
            float C = s0 / expf(sl[0] - mxl);
            float bval[NCAND];
#pragma unroll
            for (int j = 0; j < NCAND; ++j)
                bval[j] = expf(sl[j] - mxl) * C + sbias_g[se[j]];

            int ix[TOPK];
            unsigned m2 = 0;
#pragma unroll
            for (int k = 0; k < TOPK; ++k) {
                float best = -1e30f;
                int bj = 0, beste = NEXP;
                for (int j = 0; j < NCAND; ++j) {
                    if (!((m2 >> j) & 1u)) {
                        float v = bval[j];
                        int e = se[j];
                        if (v > best || (v == best && e < beste)) {
                            best = v; bj = j; beste = e;
                        }
                    }
                }
                m2 |= 1u << bj;
                ix[k] = se[bj];
            }
            float w[TOPK], ss = 0.0f;
#pragma unroll
            for (int k = 0; k < TOPK; ++k) {
                w[k] = out[OFF_SCORES + (size_t)tok * NEXP + ix[k]];
                ss += w[k] * w[k];
            }
            float winv = 1.0f / sqrtf(ss);
            float* gW = out + OFF_W   + (size_t)tok * TOPK;
            float* gI = out + OFF_IDX + (size_t)tok * TOPK;
#pragma unroll
            for (int k = 0; k < TOPK; ++k) {
                gW[k] = w[k] * winv;
                gI[k] = (float)ix[k];
            }
        }
    }
}

__global__ void bincount_kernel(const float* __restrict__ gI, float* __restrict__ cnt) {
    __shared__ int h[NEXP];
    const int tid = threadIdx.x;
    if (tid < NEXP) h[tid] = 0;
    __syncthreads();
    for (int idx = blockIdx.x * blockDim.x + tid; idx < N_TOK * TOPK;
         idx += gridDim.x * blockDim.x)
        atomicAdd(&h[(int)gI[idx]], 1);
    __syncthreads();
    if (tid < NEXP && h[tid]) atomicAdd(&cnt[tid], (float)h[tid]);
}

extern "C" void kernel_launch(void* const* d_in, const int* in_sizes, int n_in,
                              void* d_out, int out_size) {
    const float* x     = (const float*)d_in[0];
    const float* W     = (const float*)d_in[1];
    const float* sbias = (const float*)d_in[2];
    const float* noise = (const float*)d_in[3];
    float* out = (float*)d_out;

    cudaFuncSetAttribute(router_kernel, cudaFuncAttributeMaxDynamicSharedMemorySize,
                         SMEM_BYTES);

    zero_cnt_kernel<<<1, NEXP>>>(out + OFF_CNT);
    prep_W_kernel<<<(NCHUNK * 16 * NEXP) / 256, 256>>>(W);
    router_kernel<<<NBLK, THREADS, SMEM_BYTES>>>(x, sbias, noise, out);
    repair_kernel<<<256, 384>>>(x, sbias, noise, out);
    bincount_kernel<<<64, 256>>>(out + OFF_IDX, out + OFF_CNT);
}

// round 8
// speedup vs baseline: 1.2896x; 1.2896x over previous
#include <cuda_runtime.h>
#include <cuda_bf16.h>
#include <cstdint>

// MoE router: jitter -> GEMM (16384x4096 @ 4096x64) -> softmax -> biased top-8
// -> L2-norm weights -> bincount.  GEMM via mma.sync.m16n8k16.bf16, 3xBF16
// split.  MT=64, 2 CTAs/SM (grid 256) so phase bubbles of one CTA are filled
// by the other.  B frags read directly from L2 (prep lays them out per-lane).
// Near-tie tokens repaired in exact fp32.

#define N_TOK   16384
#define DIM     4096
#define NEXP    64
#define TOPK    8
#define NCAND   12
#define MT      64
#define KC      32              // K per chunk = 16 kp words = 2 k16-steps
#define NCHUNK  (DIM / KC)      // 128
#define THREADS 256
#define NBLK    (N_TOK / MT)    // 256
#define THRESH  2e-5f

#define OFF_LOGITS 0
#define OFF_SCORES (N_TOK * NEXP)
#define OFF_W      (2 * N_TOK * NEXP)
#define OFF_IDX    (2 * N_TOK * NEXP + N_TOK * TOPK)
#define OFF_CNT    (2 * N_TOK * NEXP + 2 * N_TOK * TOPK)

// dynamic smem: A planes only, double buffered. per buf: hi 4KB + lo 4KB.
#define AHIB(b) ((b) * 8192)
#define ALOB(b) ((b) * 8192 + 4096)
#define SMEM_BYTES 17408        // max(16KB A bufs, 64*65*4 L) + pad

typedef unsigned long long u64;

// XOR'ed word index within an A plane (conflict-free for STS and frag LDS)
#define AW(kp, tok) ((kp) * 64 + ((tok) ^ (((kp) & 3) << 3)))

// B frags in exact per-lane order: [chunk][k16step][j][lane] -> uint2
__device__ uint2 g_Bhf[NCHUNK * 2 * 8 * 32];
__device__ uint2 g_Blf[NCHUNK * 2 * 8 * 32];
__device__ float g_WT[NEXP * DIM];              // [e][k] fp32 for repair
__device__ int g_nflag;
__device__ int g_list[N_TOK];
__device__ int g_cand[N_TOK * NCAND];

__device__ __forceinline__ uint32_t pack_bf16x2(float hi_elem, float lo_elem) {
    uint32_t d;
    asm("cvt.rn.bf16x2.f32 %0, %1, %2;" : "=r"(d) : "f"(hi_elem), "f"(lo_elem));
    return d;
}

__device__ __forceinline__ void mma_bf16(float* c,
                                         uint32_t a0, uint32_t a1, uint32_t a2, uint32_t a3,
                                         uint32_t b0, uint32_t b1) {
    asm volatile(
        "mma.sync.aligned.m16n8k16.row.col.f32.bf16.bf16.f32 "
        "{%0,%1,%2,%3}, {%4,%5,%6,%7}, {%8,%9}, {%0,%1,%2,%3};"
        : "+f"(c[0]), "+f"(c[1]), "+f"(c[2]), "+f"(c[3])
        : "r"(a0), "r"(a1), "r"(a2), "r"(a3), "r"(b0), "r"(b1));
}

// prep: split W into per-lane bf16 hi/lo frag layout + fp32 transpose; also
// zeroes counters (folded in so the launch sequence is 4 kernels; ncu -s 5
// then lands on the router of the second replay).
__global__ void prep_W_kernel(const float* __restrict__ W, float* __restrict__ cnt) {
    if (blockIdx.x == 0) {
        if (threadIdx.x < NEXP) cnt[threadIdx.x] = 0.0f;
        if (threadIdx.x == 0) g_nflag = 0;
    }
    int p = blockIdx.x * 256 + threadIdx.x;     // 65536
    int lane = p & 31;
    int j    = (p >> 5) & 7;
    int s    = (p >> 8) & 1;
    int c    = p >> 9;
    int g2   = lane >> 2;
    int tig  = lane & 3;
    int e    = j * 8 + g2;
    int k1 = c * KC + s * 16 + 2 * tig;         // elements k1,k1+1 ; k2,k2+1
    int k2 = k1 + 8;
    float w0 = W[(size_t)k1 * NEXP + e];
    float w1 = W[(size_t)(k1 + 1) * NEXP + e];
    float w2 = W[(size_t)k2 * NEXP + e];
    float w3 = W[(size_t)(k2 + 1) * NEXP + e];
    uint32_t h0 = pack_bf16x2(w1, w0);
    uint32_t h1 = pack_bf16x2(w3, w2);
    float r0 = w0 - __uint_as_float(h0 << 16);
    float r1 = w1 - __uint_as_float(h0 & 0xFFFF0000u);
    float r2 = w2 - __uint_as_float(h1 << 16);
    float r3 = w3 - __uint_as_float(h1 & 0xFFFF0000u);
    uint32_t l0 = pack_bf16x2(r1, r0);
    uint32_t l1 = pack_bf16x2(r3, r2);
    g_Bhf[p] = make_uint2(h0, h1);
    g_Blf[p] = make_uint2(l0, l1);
    g_WT[(size_t)e * DIM + k1]     = w0;
    g_WT[(size_t)e * DIM + k1 + 1] = w1;
    g_WT[(size_t)e * DIM + k2]     = w2;
    g_WT[(size_t)e * DIM + k2 + 1] = w3;
}

__global__ void __launch_bounds__(THREADS, 2)
router_kernel(const float* __restrict__ x, const float* __restrict__ sbias_g,
              const float* __restrict__ noise, float* __restrict__ out) {
    extern __shared__ char db[];
    __shared__ float s_bias[NEXP];

    const int tid  = threadIdx.x;
    const int wid  = tid >> 5;
    const int lane = tid & 31;
    const int g    = lane >> 2;
    const int tig  = lane & 3;
    const int set  = wid >> 2;                // K-set: which k16 step of chunk
    const int wTok = (wid & 3) * 16;          // warp token base (m16 tile)
    const int tok0 = blockIdx.x * MT;

    if (tid < NEXP) s_bias[tid] = sbias_g[tid];

    // staging: thread -> (token 0..63, k-quarter of 8 elems = 4 kp)
    const int t_tok = tid & 63;
    const int t_q   = tid >> 6;               // 0..3
    const float* xg = x     + (size_t)(tok0 + t_tok) * DIM + t_q * 8;
    const float* ng = noise + (size_t)(tok0 + t_tok) * DIM + t_q * 8;

    float acc[8][4];
#pragma unroll
    for (int j = 0; j < 8; ++j)
#pragma unroll
        for (int q = 0; q < 4; ++q) acc[j][q] = 0.0f;

    float4 rx[2], rn[2];
#pragma unroll
    for (int j = 0; j < 2; ++j) {
        rx[j] = *(const float4*)(xg + 4 * j);
        rn[j] = *(const float4*)(ng + 4 * j);
    }

#define STORE_CHUNK(BUF) do {                                                   \
        uint32_t* Ah = (uint32_t*)(db + AHIB(BUF));                             \
        uint32_t* Al = (uint32_t*)(db + ALOB(BUF));                             \
        _Pragma("unroll")                                                       \
        for (int j = 0; j < 2; ++j) {                                           \
            float v0 = rx[j].x * (0.99f + rn[j].x * 0.02f);                     \
            float v1 = rx[j].y * (0.99f + rn[j].y * 0.02f);                     \
            float v2 = rx[j].z * (0.99f + rn[j].z * 0.02f);                     \
            float v3 = rx[j].w * (0.99f + rn[j].w * 0.02f);                     \
            uint32_t h0 = pack_bf16x2(v1, v0);                                  \
            uint32_t h1 = pack_bf16x2(v3, v2);                                  \
            float r0 = v0 - __uint_as_float(h0 << 16);                          \
            float r1 = v1 - __uint_as_float(h0 & 0xFFFF0000u);                  \
            float r2 = v2 - __uint_as_float(h1 << 16);                          \
            float r3 = v3 - __uint_as_float(h1 & 0xFFFF0000u);                  \
            uint32_t l0 = pack_bf16x2(r1, r0);                                  \
            uint32_t l1 = pack_bf16x2(r3, r2);                                  \
            int kp0 = t_q * 4 + 2 * j;                                          \
            Ah[AW(kp0, t_tok)]     = h0;                                        \
            Ah[AW(kp0 + 1, t_tok)] = h1;                                        \
            Al[AW(kp0, t_tok)]     = l0;                                        \
            Al[AW(kp0 + 1, t_tok)] = l1;                                        \
        }                                                                       \
    } while (0)

    STORE_CHUNK(0);
    __syncthreads();

#pragma unroll 1
    for (int c = 0; c < NCHUNK; ++c) {
        const int buf = c & 1;
        const bool more = (c + 1 < NCHUNK);

        if (more) {
            const int cb = (c + 1) * KC;
#pragma unroll
            for (int j = 0; j < 2; ++j) {
                rx[j] = *(const float4*)(xg + cb + 4 * j);
                rn[j] = *(const float4*)(ng + cb + 4 * j);
            }
        }

        // ---- my k16 step: B frags straight from L2, A frags from smem ----
        {
            const uint2* Bh = g_Bhf + ((size_t)(c * 2 + set) * 8) * 32 + lane;
            const uint2* Bl = g_Blf + ((size_t)(c * 2 + set) * 8) * 32 + lane;
            uint2 bh[8], bl[8];
#pragma unroll
            for (int j = 0; j < 8; ++j) bh[j] = __ldg(Bh + j * 32);
#pragma unroll
            for (int j = 0; j < 8; ++j) bl[j] = __ldg(Bl + j * 32);

            const uint32_t* Ah = (const uint32_t*)(db + AHIB(buf));
            const uint32_t* Al = (const uint32_t*)(db + ALOB(buf));
            const int kb = set * 8;
            const int tr = wTok + g;
            uint32_t ah[4], al[4];
            ah[0] = Ah[AW(kb + tig, tr)];
            ah[1] = Ah[AW(kb + tig, tr + 8)];
            ah[2] = Ah[AW(kb + tig + 4, tr)];
            ah[3] = Ah[AW(kb + tig + 4, tr + 8)];
            al[0] = Al[AW(kb + tig, tr)];
            al[1] = Al[AW(kb + tig, tr + 8)];
            al[2] = Al[AW(kb + tig + 4, tr)];
            al[3] = Al[AW(kb + tig + 4, tr + 8)];

            // T1: a_hi * b_hi
#pragma unroll
            for (int j = 0; j < 8; ++j)
                mma_bf16(acc[j], ah[0], ah[1], ah[2], ah[3], bh[j].x, bh[j].y);
            // T3: a_lo * b_hi
#pragma unroll
            for (int j = 0; j < 8; ++j)
                mma_bf16(acc[j], al[0], al[1], al[2], al[3], bh[j].x, bh[j].y);
            // T2: a_hi * b_lo
#pragma unroll
            for (int j = 0; j < 8; ++j)
                mma_bf16(acc[j], ah[0], ah[1], ah[2], ah[3], bl[j].x, bl[j].y);
        }

        if (more) {
            __syncthreads();          // everyone done reading buf^1 from 2 chunks ago
            STORE_CHUNK(buf ^ 1);
            __syncthreads();
        }
    }

    // ---- epilogue: K-set reduction into L[64][65] ----
    __syncthreads();
    float* L = (float*)db;
    if (set == 0) {
#pragma unroll
        for (int j = 0; j < 8; ++j) {
            int r = wTok + g, cb = j * 8 + tig * 2;
            L[r * 65 + cb]           = acc[j][0];
            L[r * 65 + cb + 1]       = acc[j][1];
            L[(r + 8) * 65 + cb]     = acc[j][2];
            L[(r + 8) * 65 + cb + 1] = acc[j][3];
        }
    }
    __syncthreads();
    if (set == 1) {
#pragma unroll
        for (int j = 0; j < 8; ++j) {
            int r = wTok + g, cb = j * 8 + tig * 2;
            L[r * 65 + cb]           += acc[j][0];
            L[r * 65 + cb + 1]       += acc[j][1];
            L[(r + 8) * 65 + cb]     += acc[j][2];
            L[(r + 8) * 65 + cb + 1] += acc[j][3];
        }
    }
    __syncthreads();

    float* gL = out + OFF_LOGITS + (size_t)tok0 * NEXP;
    for (int idx = tid; idx < MT * NEXP; idx += THREADS)
        gL[idx] = L[(idx >> 6) * 65 + (idx & 63)];
    __syncthreads();

    if (tid < MT) {
        float* row = L + tid * 65;
        float mx = row[0];
#pragma unroll 8
        for (int e = 1; e < NEXP; ++e) mx = fmaxf(mx, row[e]);
        float s = 0.0f;
#pragma unroll 8
        for (int e = 0; e < NEXP; ++e) s += expf(row[e] - mx);
        float inv = 1.0f / s;
#pragma unroll 8
        for (int e = 0; e < NEXP; ++e) row[e] = expf(row[e] - mx) * inv;
    }
    __syncthreads();

    float* gS = out + OFF_SCORES + (size_t)tok0 * NEXP;
    for (int idx = tid; idx < MT * NEXP; idx += THREADS)
        gS[idx] = L[(idx >> 6) * 65 + (idx & 63)];

    // top-12 biased ranking; write top-8; flag near-ties for exact-fp32 repair
    if (tid < MT) {
        const float* rp = L + tid * 65;
        float bv[NCAND];
        int   bix[NCAND];
        u64 mask = 0ull;
#pragma unroll
        for (int k = 0; k < NCAND; ++k) {
            float best = -1e30f;
            int bi = 0;
            for (int e = 0; e < NEXP; ++e) {
                if (!((mask >> e) & 1ull)) {
                    float v = rp[e] + s_bias[e];
                    if (v > best) { best = v; bi = e; }
                }
            }
            mask |= 1ull << bi;
            bv[k] = best;
            bix[k] = bi;
        }
        float w[TOPK], ss = 0.0f;
#pragma unroll
        for (int k = 0; k < TOPK; ++k) { w[k] = rp[bix[k]]; ss += w[k] * w[k]; }
        float winv = 1.0f / sqrtf(ss);

        const int tok = tok0 + tid;
        float* gW = out + OFF_W   + (size_t)tok * TOPK;
        float* gI = out + OFF_IDX + (size_t)tok * TOPK;
#pragma unroll
        for (int k = 0; k < TOPK; ++k) {
            gW[k] = w[k] * winv;
            gI[k] = (float)bix[k];
        }

        float ming = bv[0] - bv[1];
#pragma unroll
        for (int j = 1; j < 8; ++j) ming = fminf(ming, bv[j] - bv[j + 1]);
        if (ming < THRESH) {
            int pos = atomicAdd(&g_nflag, 1);
            g_list[pos] = tok;
#pragma unroll
            for (int j = 0; j < NCAND; ++j) g_cand[tok * NCAND + j] = bix[j];
        }
    }
}

// Repair: recompute 12 candidate logits in exact fp32 for flagged tokens,
// re-rank, rewrite indices + weights (weights gathered from MMA scores row).
__global__ void __launch_bounds__(384, 2)
repair_kernel(const float* __restrict__ x, const float* __restrict__ sbias_g,
              const float* __restrict__ noise, float* __restrict__ out) {
    __shared__ float sxj[DIM];
    __shared__ float sl[NCAND];
    __shared__ int   se[NCAND];

    const int tid  = threadIdx.x;
    const int wid  = tid >> 5;
    const int lane = tid & 31;
    const int n    = g_nflag;

    for (int i = blockIdx.x; i < n; i += gridDim.x) {
        const int tok = g_list[i];
        __syncthreads();

        const float* xr = x     + (size_t)tok * DIM;
        const float* nr = noise + (size_t)tok * DIM;
        for (int idx = tid; idx < DIM; idx += 384)
            sxj[idx] = xr[idx] * (0.99f + nr[idx] * 0.02f);
        __syncthreads();

        if (wid < NCAND) {
            const int e = g_cand[tok * NCAND + wid];
            const float* wt = g_WT + (size_t)e * DIM;
            float a = 0.0f;
            for (int k = lane; k < DIM; k += 32 * 4) {
                a += sxj[k]       * wt[k];
                a += sxj[k + 32]  * wt[k + 32];
                a += sxj[k + 64]  * wt[k + 64];
                a += sxj[k + 96]  * wt[k + 96];
            }
#pragma unroll
            for (int o = 16; o; o >>= 1) a += __shfl_xor_sync(0xFFFFFFFFu, a, o);
            if (lane == 0) { sl[wid] = a; se[wid] = e; }
        }
        __syncthreads();

        if (tid == 0) {
            float mxl = sl[0];
#pragma unroll
            for (int j = 1; j < NCAND; ++j) mxl = fmaxf(mxl, sl[j]);
            float s0 = out[OFF_SCORES + (size_t)tok * NEXP + se[0]];
            float C = s0 / expf(sl[0] - mxl);
            float bval[NCAND];
#pragma unroll
            for (int j = 0; j < NCAND; ++j)
                bval[j] = expf(sl[j] - mxl) * C + sbias_g[se[j]];

            int ix[TOPK];
            unsigned m2 = 0;
#pragma unroll
            for (int k = 0; k < TOPK; ++k) {
                float best = -1e30f;
                int bj = 0, beste = NEXP;
                for (int j = 0; j < NCAND; ++j) {
                    if (!((m2 >> j) & 1u)) {
                        float v = bval[j];
                        int e = se[j];
                        if (v > best || (v == best && e < beste)) {
                            best = v; bj = j; beste = e;
                        }
                    }
                }
                m2 |= 1u << bj;
                ix[k] = se[bj];
            }
            float w[TOPK], ss = 0.0f;
#pragma unroll
            for (int k = 0; k < TOPK; ++k) {
                w[k] = out[OFF_SCORES + (size_t)tok * NEXP + ix[k]];
                ss += w[k] * w[k];
            }
            float winv = 1.0f / sqrtf(ss);
            float* gW = out + OFF_W   + (size_t)tok * TOPK;
            float* gI = out + OFF_IDX + (size_t)tok * TOPK;
#pragma unroll
            for (int k = 0; k < TOPK; ++k) {
                gW[k] = w[k] * winv;
                gI[k] = (float)ix[k];
            }
        }
    }
}

__global__ void bincount_kernel(const float* __restrict__ gI, float* __restrict__ cnt) {
    __shared__ int h[NEXP];
    const int tid = threadIdx.x;
    if (tid < NEXP) h[tid] = 0;
    __syncthreads();
    for (int idx = blockIdx.x * blockDim.x + tid; idx < N_TOK * TOPK;
         idx += gridDim.x * blockDim.x)
        atomicAdd(&h[(int)gI[idx]], 1);
    __syncthreads();
    if (tid < NEXP && h[tid]) atomicAdd(&cnt[tid], (float)h[tid]);
}

extern "C" void kernel_launch(void* const* d_in, const int* in_sizes, int n_in,
                              void* d_out, int out_size) {
    const float* x     = (const float*)d_in[0];
    const float* W     = (const float*)d_in[1];
    const float* sbias = (const float*)d_in[2];
    const float* noise = (const float*)d_in[3];
    float* out = (float*)d_out;

    prep_W_kernel<<<(NCHUNK * 2 * 8 * 32) / 256, 256>>>(W, out + OFF_CNT);
    router_kernel<<<NBLK, THREADS, SMEM_BYTES>>>(x, sbias, noise, out);
    repair_kernel<<<256, 384>>>(x, sbias, noise, out);
    bincount_kernel<<<64, 256>>>(out + OFF_IDX, out + OFF_CNT);
}

// round 9
// speedup vs baseline: 1.4367x; 1.1141x over previous
#include <cuda_runtime.h>
#include <cuda_bf16.h>
#include <cstdint>

// MoE router: jitter -> GEMM (16384x4096 @ 4096x64) -> softmax -> biased top-8
// -> L2-norm weights -> bincount.  GEMM via mma.sync.m16n8k16.bf16, 3xBF16
// split.  MT=32, 4 CTAs/SM (grid 512, 128 thr): per-SMSP 4 independent CTAs
// interleave so barrier/staging phases of one are covered by the others.
// One __syncthreads per K-chunk (disjoint double buffers). B frags from L2.
// Near-tie tokens repaired in exact fp32.

#define N_TOK   16384
#define DIM     4096
#define NEXP    64
#define TOPK    8
#define NCAND   12
#define MT      32
#define KC      32              // K per chunk = 16 kp words = 2 k16-steps
#define NCHUNK  (DIM / KC)      // 128
#define THREADS 128
#define NBLK    (N_TOK / MT)    // 512
#define THRESH  2e-5f

#define OFF_LOGITS 0
#define OFF_SCORES (N_TOK * NEXP)
#define OFF_W      (2 * N_TOK * NEXP)
#define OFF_IDX    (2 * N_TOK * NEXP + N_TOK * TOPK)
#define OFF_CNT    (2 * N_TOK * NEXP + 2 * N_TOK * TOPK)

// dynamic smem: A planes, double buffered. per buf: hi 2KB + lo 2KB.
#define AHIB(b) ((b) * 4096)
#define ALOB(b) ((b) * 4096 + 2048)
#define SMEM_BYTES 8448         // max(8192 A bufs, 32*65*4=8320 L) + pad

typedef unsigned long long u64;

// XOR'ed word index within an A plane (conflict-free for STS and frag LDS)
#define AW(kp, tok) ((kp) * 32 + ((tok) ^ (((kp) & 3) << 3)))

// B frags in exact per-lane order: [chunk][k16step][j][lane] -> uint2
__device__ uint2 g_Bhf[NCHUNK * 2 * 8 * 32];
__device__ uint2 g_Blf[NCHUNK * 2 * 8 * 32];
__device__ float g_WT[NEXP * DIM];              // [e][k] fp32 for repair
__device__ int g_nflag;
__device__ int g_list[N_TOK];
__device__ int g_cand[N_TOK * NCAND];

__device__ __forceinline__ uint32_t pack_bf16x2(float hi_elem, float lo_elem) {
    uint32_t d;
    asm("cvt.rn.bf16x2.f32 %0, %1, %2;" : "=r"(d) : "f"(hi_elem), "f"(lo_elem));
    return d;
}

__device__ __forceinline__ void mma_bf16(float* c,
                                         uint32_t a0, uint32_t a1, uint32_t a2, uint32_t a3,
                                         uint32_t b0, uint32_t b1) {
    asm volatile(
        "mma.sync.aligned.m16n8k16.row.col.f32.bf16.bf16.f32 "
        "{%0,%1,%2,%3}, {%4,%5,%6,%7}, {%8,%9}, {%0,%1,%2,%3};"
        : "+f"(c[0]), "+f"(c[1]), "+f"(c[2]), "+f"(c[3])
        : "r"(a0), "r"(a1), "r"(a2), "r"(a3), "r"(b0), "r"(b1));
}

// prep: split W into per-lane bf16 hi/lo frag layout + fp32 transpose; zeroes
// counters/flags.
__global__ void prep_W_kernel(const float* __restrict__ W, float* __restrict__ cnt) {
    if (blockIdx.x == 0) {
        if (threadIdx.x < NEXP) cnt[threadIdx.x] = 0.0f;
        if (threadIdx.x == 0) g_nflag = 0;
    }
    int p = blockIdx.x * 256 + threadIdx.x;     // 65536
    int lane = p & 31;
    int j    = (p >> 5) & 7;
    int s    = (p >> 8) & 1;
    int c    = p >> 9;
    int g2   = lane >> 2;
    int tig  = lane & 3;
    int e    = j * 8 + g2;
    int k1 = c * KC + s * 16 + 2 * tig;
    int k2 = k1 + 8;
    float w0 = W[(size_t)k1 * NEXP + e];
    float w1 = W[(size_t)(k1 + 1) * NEXP + e];
    float w2 = W[(size_t)k2 * NEXP + e];
    float w3 = W[(size_t)(k2 + 1) * NEXP + e];
    uint32_t h0 = pack_bf16x2(w1, w0);
    uint32_t h1 = pack_bf16x2(w3, w2);
    float r0 = w0 - __uint_as_float(h0 << 16);
    float r1 = w1 - __uint_as_float(h0 & 0xFFFF0000u);
    float r2 = w2 - __uint_as_float(h1 << 16);
    float r3 = w3 - __uint_as_float(h1 & 0xFFFF0000u);
    uint32_t l0 = pack_bf16x2(r1, r0);
    uint32_t l1 = pack_bf16x2(r3, r2);
    g_Bhf[p] = make_uint2(h0, h1);
    g_Blf[p] = make_uint2(l0, l1);
    g_WT[(size_t)e * DIM + k1]     = w0;
    g_WT[(size_t)e * DIM + k1 + 1] = w1;
    g_WT[(size_t)e * DIM + k2]     = w2;
    g_WT[(size_t)e * DIM + k2 + 1] = w3;
}

__global__ void __launch_bounds__(THREADS, 4)
router_kernel(const float* __restrict__ x, const float* __restrict__ sbias_g,
              const float* __restrict__ noise, float* __restrict__ out) {
    extern __shared__ char db[];
    __shared__ float s_bias[NEXP];

    const int tid  = threadIdx.x;
    const int wid  = tid >> 5;
    const int lane = tid & 31;
    const int g    = lane >> 2;
    const int tig  = lane & 3;
    const int set  = wid >> 1;                // K-set: which k16 step of chunk
    const int wTok = (wid & 1) * 16;          // warp token base (m16 tile)
    const int tok0 = blockIdx.x * MT;

    if (tid < NEXP) s_bias[tid] = sbias_g[tid];

    // staging: thread -> (token 0..31, k-quarter of 8 elems = 4 kp)
    const int t_tok = tid & 31;
    const int t_q   = tid >> 5;               // 0..3
    const float* xg = x     + (size_t)(tok0 + t_tok) * DIM + t_q * 8;
    const float* ng = noise + (size_t)(tok0 + t_tok) * DIM + t_q * 8;

    float acc[8][4];
#pragma unroll
    for (int j = 0; j < 8; ++j)
#pragma unroll
        for (int q = 0; q < 4; ++q) acc[j][q] = 0.0f;

    float4 rx[2], rn[2];
#pragma unroll
    for (int j = 0; j < 2; ++j) {
        rx[j] = *(const float4*)(xg + 4 * j);
        rn[j] = *(const float4*)(ng + 4 * j);
    }

#define STORE_CHUNK(BUF) do {                                                   \
        uint32_t* Ah = (uint32_t*)(db + AHIB(BUF));                             \
        uint32_t* Al = (uint32_t*)(db + ALOB(BUF));                             \
        _Pragma("unroll")                                                       \
        for (int j = 0; j < 2; ++j) {                                           \
            float v0 = rx[j].x * (0.99f + rn[j].x * 0.02f);                     \
            float v1 = rx[j].y * (0.99f + rn[j].y * 0.02f);                     \
            float v2 = rx[j].z * (0.99f + rn[j].z * 0.02f);                     \
            float v3 = rx[j].w * (0.99f + rn[j].w * 0.02f);                     \
            uint32_t h0 = pack_bf16x2(v1, v0);                                  \
            uint32_t h1 = pack_bf16x2(v3, v2);                                  \
            float r0 = v0 - __uint_as_float(h0 << 16);                          \
            float r1 = v1 - __uint_as_float(h0 & 0xFFFF0000u);                  \
            float r2 = v2 - __uint_as_float(h1 << 16);                          \
            float r3 = v3 - __uint_as_float(h1 & 0xFFFF0000u);                  \
            uint32_t l0 = pack_bf16x2(r1, r0);                                  \
            uint32_t l1 = pack_bf16x2(r3, r2);                                  \
            int kp0 = t_q * 4 + 2 * j;                                          \
            Ah[AW(kp0, t_tok)]     = h0;                                        \
            Ah[AW(kp0 + 1, t_tok)] = h1;                                        \
            Al[AW(kp0, t_tok)]     = l0;                                        \
            Al[AW(kp0 + 1, t_tok)] = l1;                                        \
        }                                                                       \
    } while (0)

    STORE_CHUNK(0);
    __syncthreads();

#pragma unroll 1
    for (int c = 0; c < NCHUNK; ++c) {
        const int buf = c & 1;
        const bool more = (c + 1 < NCHUNK);

        if (more) {
            const int cb = (c + 1) * KC;
#pragma unroll
            for (int j = 0; j < 2; ++j) {
                rx[j] = *(const float4*)(xg + cb + 4 * j);
                rn[j] = *(const float4*)(ng + cb + 4 * j);
            }
        }

        // ---- my k16 step: B frags straight from L2, A frags from smem ----
        {
            const uint2* Bh = g_Bhf + ((size_t)(c * 2 + set) * 8) * 32 + lane;
            const uint2* Bl = g_Blf + ((size_t)(c * 2 + set) * 8) * 32 + lane;
            uint2 b[8];
#pragma unroll
            for (int j = 0; j < 8; ++j) b[j] = __ldg(Bh + j * 32);

            const uint32_t* Ah = (const uint32_t*)(db + AHIB(buf));
            const uint32_t* Al = (const uint32_t*)(db + ALOB(buf));
            const int kb = set * 8;
            const int tr = wTok + g;
            uint32_t ah[4], al[4];
            ah[0] = Ah[AW(kb + tig, tr)];
            ah[1] = Ah[AW(kb + tig, tr + 8)];
            ah[2] = Ah[AW(kb + tig + 4, tr)];
            ah[3] = Ah[AW(kb + tig + 4, tr + 8)];
            al[0] = Al[AW(kb + tig, tr)];
            al[1] = Al[AW(kb + tig, tr + 8)];
            al[2] = Al[AW(kb + tig + 4, tr)];
            al[3] = Al[AW(kb + tig + 4, tr + 8)];

            // T1: a_hi * b_hi
#pragma unroll
            for (int j = 0; j < 8; ++j)
                mma_bf16(acc[j], ah[0], ah[1], ah[2], ah[3], b[j].x, b[j].y);
            // T3: a_lo * b_hi
#pragma unroll
            for (int j = 0; j < 8; ++j)
                mma_bf16(acc[j], al[0], al[1], al[2], al[3], b[j].x, b[j].y);
            // T2: a_hi * b_lo (reuse b regs)
#pragma unroll
            for (int j = 0; j < 8; ++j) b[j] = __ldg(Bl + j * 32);
#pragma unroll
            for (int j = 0; j < 8; ++j)
                mma_bf16(acc[j], ah[0], ah[1], ah[2], ah[3], b[j].x, b[j].y);
        }

        // store chunk c+1 into buf^1 (disjoint from buf being read this chunk;
        // prior readers of buf^1 were fenced by chunk c-1's barrier)
        if (more) STORE_CHUNK(buf ^ 1);
        __syncthreads();
    }

    // ---- epilogue: K-set reduction into L[32][65] ----
    float* L = (float*)db;
    if (set == 0) {
#pragma unroll
        for (int j = 0; j < 8; ++j) {
            int r = wTok + g, cb = j * 8 + tig * 2;
            L[r * 65 + cb]           = acc[j][0];
            L[r * 65 + cb + 1]       = acc[j][1];
            L[(r + 8) * 65 + cb]     = acc[j][2];
            L[(r + 8) * 65 + cb + 1] = acc[j][3];
        }
    }
    __syncthreads();
    if (set == 1) {
#pragma unroll
        for (int j = 0; j < 8; ++j) {
            int r = wTok + g, cb = j * 8 + tig * 2;
            L[r * 65 + cb]           += acc[j][0];
            L[r * 65 + cb + 1]       += acc[j][1];
            L[(r + 8) * 65 + cb]     += acc[j][2];
            L[(r + 8) * 65 + cb + 1] += acc[j][3];
        }
    }
    __syncthreads();

    float* gL = out + OFF_LOGITS + (size_t)tok0 * NEXP;
    for (int idx = tid; idx < MT * NEXP; idx += THREADS)
        gL[idx] = L[(idx >> 6) * 65 + (idx & 63)];
    __syncthreads();

    if (tid < MT) {
        float* row = L + tid * 65;
        float mx = row[0];
#pragma unroll 8
        for (int e = 1; e < NEXP; ++e) mx = fmaxf(mx, row[e]);
        float s = 0.0f;
#pragma unroll 8
        for (int e = 0; e < NEXP; ++e) s += expf(row[e] - mx);
        float inv = 1.0f / s;
#pragma unroll 8
        for (int e = 0; e < NEXP; ++e) row[e] = expf(row[e] - mx) * inv;
    }
    __syncthreads();

    float* gS = out + OFF_SCORES + (size_t)tok0 * NEXP;
    for (int idx = tid; idx < MT * NEXP; idx += THREADS)
        gS[idx] = L[(idx >> 6) * 65 + (idx & 63)];

    // top-12 biased ranking; write top-8; flag near-ties for exact-fp32 repair
    if (tid < MT) {
        const float* rp = L + tid * 65;
        float bv[NCAND];
        int   bix[NCAND];
        u64 mask = 0ull;
#pragma unroll
        for (int k = 0; k < NCAND; ++k) {
            float best = -1e30f;
            int bi = 0;
            for (int e = 0; e < NEXP; ++e) {
                if (!((mask >> e) & 1ull)) {
                    float v = rp[e] + s_bias[e];
                    if (v > best) { best = v; bi = e; }
                }
            }
            mask |= 1ull << bi;
            bv[k] = best;
            bix[k] = bi;
        }
        float w[TOPK], ss = 0.0f;
#pragma unroll
        for (int k = 0; k < TOPK; ++k) { w[k] = rp[bix[k]]; ss += w[k] * w[k]; }
        float winv = 1.0f / sqrtf(ss);

        const int tok = tok0 + tid;
        float* gW = out + OFF_W   + (size_t)tok * TOPK;
        float* gI = out + OFF_IDX + (size_t)tok * TOPK;
#pragma unroll
        for (int k = 0; k < TOPK; ++k) {
            gW[k] = w[k] * winv;
            gI[k] = (float)bix[k];
        }

        float ming = bv[0] - bv[1];
#pragma unroll
        for (int j = 1; j < 8; ++j) ming = fminf(ming, bv[j] - bv[j + 1]);
        if (ming < THRESH) {
            int pos = atomicAdd(&g_nflag, 1);
            g_list[pos] = tok;
#pragma unroll
            for (int j = 0; j < NCAND; ++j) g_cand[tok * NCAND + j] = bix[j];
        }
    }
}

// Repair: recompute 12 candidate logits in exact fp32 for flagged tokens,
// re-rank, rewrite indices + weights (weights gathered from MMA scores row).
__global__ void __launch_bounds__(384, 2)
repair_kernel(const float* __restrict__ x, const float* __restrict__ sbias_g,
              const float* __restrict__ noise, float* __restrict__ out) {
    __shared__ float sxj[DIM];
    __shared__ float sl[NCAND];
    __shared__ int   se[NCAND];

    const int tid  = threadIdx.x;
    const int wid  = tid >> 5;
    const int lane = tid & 31;
    const int n    = g_nflag;

    for (int i = blockIdx.x; i < n; i += gridDim.x) {
        const int tok = g_list[i];
        __syncthreads();

        const float* xr = x     + (size_t)tok * DIM;
        const float* nr = noise + (size_t)tok * DIM;
        for (int idx = tid; idx < DIM; idx += 384)
            sxj[idx] = xr[idx] * (0.99f + nr[idx] * 0.02f);
        __syncthreads();

        if (wid < NCAND) {
            const int e = g_cand[tok * NCAND + wid];
            const float* wt = g_WT + (size_t)e * DIM;
            float a = 0.0f;
            for (int k = lane; k < DIM; k += 32 * 4) {
                a += sxj[k]       * wt[k];
                a += sxj[k + 32]  * wt[k + 32];
                a += sxj[k + 64]  * wt[k + 64];
                a += sxj[k + 96]  * wt[k + 96];
            }
#pragma unroll
            for (int o = 16; o; o >>= 1) a += __shfl_xor_sync(0xFFFFFFFFu, a, o);
            if (lane == 0) { sl[wid] = a; se[wid] = e; }
        }
        __syncthreads();

        if (tid == 0) {
            float mxl = sl[0];
#pragma unroll
            for (int j = 1; j < NCAND; ++j) mxl = fmaxf(mxl, sl[j]);
            float s0 = out[OFF_SCORES + (size_t)tok * NEXP + se[0]];
            float C = s0 / expf(sl[0] - mxl);
            float bval[NCAND];
#pragma unroll
            for (int j = 0; j < NCAND; ++j)
                bval[j] = expf(sl[j] - mxl) * C + sbias_g[se[j]];

            int ix[TOPK];
            unsigned m2 = 0;
#pragma unroll
            for (int k = 0; k < TOPK; ++k) {
                float best = -1e30f;
                int bj = 0, beste = NEXP;
                for (int j = 0; j < NCAND; ++j) {
                    if (!((m2 >> j) & 1u)) {
                        float v = bval[j];
                        int e = se[j];
                        if (v > best || (v == best && e < beste)) {
                            best = v; bj = j; beste = e;
                        }
                    }
                }
                m2 |= 1u << bj;
                ix[k] = se[bj];
            }
            float w[TOPK], ss = 0.0f;
#pragma unroll
            for (int k = 0; k < TOPK; ++k) {
                w[k] = out[OFF_SCORES + (size_t)tok * NEXP + ix[k]];
                ss += w[k] * w[k];
            }
            float winv = 1.0f / sqrtf(ss);
            float* gW = out + OFF_W   + (size_t)tok * TOPK;
            float* gI = out + OFF_IDX + (size_t)tok * TOPK;
#pragma unroll
            for (int k = 0; k < TOPK; ++k) {
                gW[k] = w[k] * winv;
                gI[k] = (float)ix[k];
            }
        }
    }
}

__global__ void bincount_kernel(const float* __restrict__ gI, float* __restrict__ cnt) {
    __shared__ int h[NEXP];
    const int tid = threadIdx.x;
    if (tid < NEXP) h[tid] = 0;
    __syncthreads();
    for (int idx = blockIdx.x * blockDim.x + tid; idx < N_TOK * TOPK;
         idx += gridDim.x * blockDim.x)
        atomicAdd(&h[(int)gI[idx]], 1);
    __syncthreads();
    if (tid < NEXP && h[tid]) atomicAdd(&cnt[tid], (float)h[tid]);
}

extern "C" void kernel_launch(void* const* d_in, const int* in_sizes, int n_in,
                              void* d_out, int out_size) {
    const float* x     = (const float*)d_in[0];
    const float* W     = (const float*)d_in[1];
    const float* sbias = (const float*)d_in[2];
    const float* noise = (const float*)d_in[3];
    float* out = (float*)d_out;

    prep_W_kernel<<<(NCHUNK * 2 * 8 * 32) / 256, 256>>>(W, out + OFF_CNT);
    router_kernel<<<NBLK, THREADS, SMEM_BYTES>>>(x, sbias, noise, out);
    repair_kernel<<<1024, 384>>>(x, sbias, noise, out);
    bincount_kernel<<<256, 256>>>(out + OFF_IDX, out + OFF_CNT);
}